// round 3
// baseline (speedup 1.0000x reference)
#include <cuda_runtime.h>

// Problem constants
#define NB       4
#define TOK      131072          // T*n tokens per batch
#define C        64
#define NROWS    16384           // n
#define SPLITS   256             // split-K blocks per batch
#define TPS      (TOK / SPLITS)  // 512 tokens per block
#define NGROUPS  2               // split-K sub-groups within a block
#define TPG      (TPS / NGROUPS) // 256 tokens per sub-group
#define STAGE_T  8               // tokens per sub-group per stage
#define NSTAGES  (TPG / STAGE_T) // 32
#define NBUF     4               // pipeline depth
#define SROWS    (NGROUPS * STAGE_T) // 16 rows per stage buffer
#define RP       68              // padded row length (floats)

// Scratch (no allocations allowed). Transposed layouts: [d][c].
__device__ float g_partial[(size_t)NB * SPLITS * C * C]; // 16 MB partials [b][s][d][c]
__device__ float g_kvT[NB * C * C];                      // [b][d][c]
__device__ float g_smT[NB * C * C];                      // [b][d][c], alpha folded in

typedef unsigned long long u64;

__device__ __forceinline__ u64 fma2(u64 a, u64 b, u64 c) {
    u64 d;
    asm("fma.rn.f32x2 %0, %1, %2, %3;" : "=l"(d) : "l"(a), "l"(b), "l"(c));
    return d;
}
__device__ __forceinline__ u64 add2(u64 a, u64 b) {
    u64 d;
    asm("add.rn.f32x2 %0, %1, %2;" : "=l"(d) : "l"(a), "l"(b));
    return d;
}
__device__ __forceinline__ float2 unpack2(u64 v) {
    float2 r;
    asm("mov.b64 {%0, %1}, %2;" : "=f"(r.x), "=f"(r.y) : "l"(v));
    return r;
}
__device__ __forceinline__ u64 swap2(u64 v) {
    float2 t = unpack2(v);
    u64 r;
    asm("mov.b64 %0, {%1, %2};" : "=l"(r) : "f"(t.y), "f"(t.x));
    return r;
}

__device__ __forceinline__ void cp16(unsigned dst, const float* src) {
    asm volatile("cp.async.ca.shared.global [%0], [%1], 16;" :: "r"(dst), "l"(src));
}
__device__ __forceinline__ void cp_commit() {
    asm volatile("cp.async.commit_group;");
}
template <int N>
__device__ __forceinline__ void cp_wait() {
    asm volatile("cp.async.wait_group %0;" :: "n"(N));
}

// ---------------------------------------------------------------------------
// Kernel A: partial kv_mul with 4-deep cp.async pipeline.
// 128-thread block = 2 split-K sub-groups of 64 threads; each sub-group's 8x8
// thread grid covers the full 64x64 output with 8c x 8d register tiles held as
// swapped-pair f32x2 accumulators:
//   accA[i][j] += {k_even,k_odd} * {v_even,v_odd}   -> S[even][even], S[odd][odd]
//   accB[i][j] += {k_even,k_odd} * {v_odd,v_even}   -> S[even][odd],  S[odd][even]
// Epilogue writes the partial TRANSPOSED as [d][c].
// ---------------------------------------------------------------------------
__global__ __launch_bounds__(128, 4) void kv_partial_kernel(
    const float* __restrict__ Kg, const float* __restrict__ Vg)
{
    __shared__ __align__(16) float s_stage[NBUF][2][SROWS][RP];  // 34,816 B
    const int BUFSTRIDE = 2 * SROWS * RP * 4;                    // bytes per buffer

    const int b   = blockIdx.y;
    const int sp  = blockIdx.x;
    const int tid = threadIdx.x;
    const int g   = tid >> 6;          // sub-group 0..1
    const int gt  = tid & 63;
    const int c0  = (gt >> 3) * 8;
    const int d0  = (gt & 7) * 8;

    // chunk mapping: 512 16B-chunks per stage, 4 per thread
    const float* src[4];
    unsigned dstb[4];
    #pragma unroll
    for (int j = 0; j < 4; ++j) {
        int ch  = tid + j * 128;       // 0..511
        int arr = ch >> 8;             // 0=K, 1=V
        int wi  = ch & 255;
        int row = wi >> 4;             // 0..15
        int c4  = wi & 15;
        int gr  = row >> 3, tl = row & 7;
        size_t tok = (size_t)b * TOK + (size_t)sp * TPS + (size_t)gr * TPG + tl;
        src[j]  = (arr == 0 ? Kg : Vg) + tok * C + c4 * 4;
        dstb[j] = (unsigned)__cvta_generic_to_shared(&s_stage[0][arr][row][c4 * 4]);
    }

    // prologue: stages 0..2 into buffers 0..2
    #pragma unroll
    for (int st = 0; st < 3; ++st) {
        #pragma unroll
        for (int j = 0; j < 4; ++j)
            cp16(dstb[j] + st * BUFSTRIDE, src[j] + (size_t)st * 512);
        cp_commit();
    }

    u64 accA[4][4], accB[4][4];
    #pragma unroll
    for (int i = 0; i < 4; ++i)
        #pragma unroll
        for (int j = 0; j < 4; ++j) { accA[i][j] = 0ull; accB[i][j] = 0ull; }

    for (int it = 0; it < NSTAGES; ++it) {
        cp_wait<2>();
        __syncthreads();
        // prefetch stage it+3 into buffer (it+3)%4 (freed: all warps finished it-1)
        if (it + 3 < NSTAGES) {
            const int buf = (it + 3) & 3;
            #pragma unroll
            for (int j = 0; j < 4; ++j)
                cp16(dstb[j] + buf * BUFSTRIDE, src[j] + (size_t)(it + 3) * 512);
        }
        cp_commit();  // unconditional: keeps wait_group<2> arithmetic valid at tail

        const int buf = it & 3;
        #pragma unroll
        for (int t = 0; t < STAGE_T; ++t) {
            const int r = g * STAGE_T + t;
            ulonglong2 ka = *(const ulonglong2*)&s_stage[buf][0][r][c0];
            ulonglong2 kb = *(const ulonglong2*)&s_stage[buf][0][r][c0 + 4];
            ulonglong2 va = *(const ulonglong2*)&s_stage[buf][1][r][d0];
            ulonglong2 vb = *(const ulonglong2*)&s_stage[buf][1][r][d0 + 4];
            u64 ku[4] = {ka.x, ka.y, kb.x, kb.y};
            u64 vu[4] = {va.x, va.y, vb.x, vb.y};
            u64 vs[4] = {swap2(va.x), swap2(va.y), swap2(vb.x), swap2(vb.y)};
            #pragma unroll
            for (int i = 0; i < 4; ++i) {
                #pragma unroll
                for (int j = 0; j < 4; ++j) {
                    accA[i][j] = fma2(ku[i], vu[j], accA[i][j]);
                    accB[i][j] = fma2(ku[i], vs[j], accB[i][j]);
                }
            }
        }
    }

    // in-block split-K reduction: group1 -> smem -> group0 adds (deterministic)
    __syncthreads();
    u64* sred = (u64*)&s_stage[0][0][0][0];   // 64 thr * 32 u64 = 16 KB
    if (g == 1) {
        u64* dst = &sred[gt * 32];
        #pragma unroll
        for (int i = 0; i < 4; ++i)
            #pragma unroll
            for (int j = 0; j < 4; ++j) {
                dst[i * 8 + j * 2]     = accA[i][j];
                dst[i * 8 + j * 2 + 1] = accB[i][j];
            }
    }
    __syncthreads();
    if (g == 0) {
        const u64* s2 = &sred[gt * 32];
        #pragma unroll
        for (int i = 0; i < 4; ++i)
            #pragma unroll
            for (int j = 0; j < 4; ++j) {
                accA[i][j] = add2(accA[i][j], s2[i * 8 + j * 2]);
                accB[i][j] = add2(accB[i][j], s2[i * 8 + j * 2 + 1]);
            }

        // transposed write: partial[d][c]
        float* outp = &g_partial[((size_t)(b * SPLITS + sp)) * (C * C)];
        #pragma unroll
        for (int j = 0; j < 4; ++j) {
            float2 a[4], bb[4];
            #pragma unroll
            for (int i = 0; i < 4; ++i) { a[i] = unpack2(accA[i][j]); bb[i] = unpack2(accB[i][j]); }
            // row d0+2j: even c -> A.x, odd c -> B.y
            *(float4*)&outp[(d0 + 2 * j) * C + c0]     = make_float4(a[0].x, bb[0].y, a[1].x, bb[1].y);
            *(float4*)&outp[(d0 + 2 * j) * C + c0 + 4] = make_float4(a[2].x, bb[2].y, a[3].x, bb[3].y);
            // row d0+2j+1: even c -> B.x, odd c -> A.y
            *(float4*)&outp[(d0 + 2 * j + 1) * C + c0]     = make_float4(bb[0].x, a[0].y, bb[1].x, a[1].y);
            *(float4*)&outp[(d0 + 2 * j + 1) * C + c0 + 4] = make_float4(bb[2].x, a[2].y, bb[3].x, a[3].y);
        }
    }
}

// ---------------------------------------------------------------------------
// Kernel B: deterministic split reduction. 4096 float4 lanes over 32 blocks.
// ---------------------------------------------------------------------------
__global__ void kv_reduce_kernel()
{
    int q = blockIdx.x * 128 + threadIdx.x;   // 0..4095 float4 index
    int b  = q >> 10;
    int e4 = q & 1023;
    const float4* p = (const float4*)&g_partial[(size_t)b * SPLITS * (C * C)] + e4;
    float4 s0 = make_float4(0.f,0.f,0.f,0.f), s1 = s0, s2 = s0, s3 = s0;
    #pragma unroll 4
    for (int i = 0; i < SPLITS; i += 4) {
        float4 t0 = p[(size_t)(i    ) * 1024];
        float4 t1 = p[(size_t)(i + 1) * 1024];
        float4 t2 = p[(size_t)(i + 2) * 1024];
        float4 t3 = p[(size_t)(i + 3) * 1024];
        s0.x += t0.x; s0.y += t0.y; s0.z += t0.z; s0.w += t0.w;
        s1.x += t1.x; s1.y += t1.y; s1.z += t1.z; s1.w += t1.w;
        s2.x += t2.x; s2.y += t2.y; s2.z += t2.z; s2.w += t2.w;
        s3.x += t3.x; s3.y += t3.y; s3.z += t3.z; s3.w += t3.w;
    }
    float4 r;
    r.x = (s0.x + s1.x) + (s2.x + s3.x);
    r.y = (s0.y + s1.y) + (s2.y + s3.y);
    r.z = (s0.z + s1.z) + (s2.z + s3.z);
    r.w = (s0.w + s1.w) + (s2.w + s3.w);
    ((float4*)g_kvT)[q] = r;
}

// ---------------------------------------------------------------------------
// Kernel C: softmax over c (contiguous rows of g_kvT), alpha folded in.
// One thread per (b, d) row: 256 threads.
// ---------------------------------------------------------------------------
__global__ void softmax_kernel(const float* __restrict__ alpha)
{
    int tid = threadIdx.x;
    const float* in  = &g_kvT[tid * C];
    float*       out = &g_smT[tid * C];

    float v[C];
    float m = -3.402823466e38f;
    #pragma unroll
    for (int c4 = 0; c4 < C; c4 += 4) {
        float4 t = *(const float4*)&in[c4];
        v[c4] = t.x; v[c4+1] = t.y; v[c4+2] = t.z; v[c4+3] = t.w;
        m = fmaxf(m, fmaxf(fmaxf(t.x, t.y), fmaxf(t.z, t.w)));
    }
    float sum = 0.f;
    #pragma unroll
    for (int c = 0; c < C; ++c) { v[c] = expf(v[c] - m); sum += v[c]; }
    float sc = alpha[0] / sum;
    #pragma unroll
    for (int c4 = 0; c4 < C; c4 += 4) {
        *(float4*)&out[c4] = make_float4(v[c4]*sc, v[c4+1]*sc, v[c4+2]*sc, v[c4+3]*sc);
    }
}

// ---------------------------------------------------------------------------
// Kernel D: out[b,r,d] = sum_c key_cur[b,r,c] * smT[b,d,c] + val_cur.
// Pair-dot over c inside f32x2 lanes: zero pack MOVs.
// 256 threads, 64 rows/block; thread = 4 rows x 4 d (16 u64 accs).
// ---------------------------------------------------------------------------
__global__ __launch_bounds__(256, 3) void out_kernel(
    const float* __restrict__ key_cur, const float* __restrict__ val_cur,
    float* __restrict__ out)
{
    __shared__ __align__(16) float s_smT[C][RP];
    __shared__ __align__(16) float s_key[C][RP];

    const int b   = blockIdx.y;
    const int rb  = blockIdx.x;        // 0..255
    const int tid = threadIdx.x;

    const float* smg = &g_smT[b * (C * C)];
    const float* kg  = &key_cur[((size_t)b * NROWS + (size_t)rb * 64) * C];
    #pragma unroll
    for (int j = 0; j < 4; ++j) {
        int q = j * 256 + tid;         // 0..1023 float4
        int row = q >> 4, c4 = q & 15;
        *(float4*)&s_smT[row][c4 * 4] = *(const float4*)&smg[q * 4];
        *(float4*)&s_key[row][c4 * 4] = *(const float4*)&kg[q * 4];
    }
    __syncthreads();

    const int rg = tid >> 4;           // 0..15 -> 4 rows
    const int dg = tid & 15;           // 0..15 -> 4 d
    const int r0 = rg * 4, d0 = dg * 4;

    u64 acc[4][4];
    #pragma unroll
    for (int i = 0; i < 4; ++i)
        #pragma unroll
        for (int j = 0; j < 4; ++j) acc[i][j] = 0ull;

    #pragma unroll 4
    for (int cq = 0; cq < 16; ++cq) {
        ulonglong2 kr[4], sv[4];
        #pragma unroll
        for (int i = 0; i < 4; ++i) kr[i] = *(const ulonglong2*)&s_key[r0 + i][cq * 4];
        #pragma unroll
        for (int j = 0; j < 4; ++j) sv[j] = *(const ulonglong2*)&s_smT[d0 + j][cq * 4];
        #pragma unroll
        for (int i = 0; i < 4; ++i)
            #pragma unroll
            for (int j = 0; j < 4; ++j) {
                acc[i][j] = fma2(kr[i].x, sv[j].x, acc[i][j]);
                acc[i][j] = fma2(kr[i].y, sv[j].y, acc[i][j]);
            }
    }

    #pragma unroll
    for (int i = 0; i < 4; ++i) {
        size_t base = ((size_t)b * NROWS + (size_t)rb * 64 + r0 + i) * C + d0;
        float4 vc = *(const float4*)&val_cur[base];
        float2 p0 = unpack2(acc[i][0]);
        float2 p1 = unpack2(acc[i][1]);
        float2 p2 = unpack2(acc[i][2]);
        float2 p3 = unpack2(acc[i][3]);
        float4 o;
        o.x = p0.x + p0.y + vc.x;
        o.y = p1.x + p1.y + vc.y;
        o.z = p2.x + p2.y + vc.z;
        o.w = p3.x + p3.y + vc.w;
        *(float4*)&out[base] = o;
    }
}

// ---------------------------------------------------------------------------
extern "C" void kernel_launch(void* const* d_in, const int* in_sizes, int n_in,
                              void* d_out, int out_size)
{
    const float* key_mem = (const float*)d_in[0];
    const float* val_mem = (const float*)d_in[1];
    const float* key_cur = (const float*)d_in[2];
    const float* val_cur = (const float*)d_in[3];
    const float* alpha   = (const float*)d_in[4];
    float* out = (float*)d_out;

    kv_partial_kernel<<<dim3(SPLITS, NB), 128>>>(key_mem, val_mem);
    kv_reduce_kernel<<<32, 128>>>();
    softmax_kernel<<<1, 256>>>(alpha);
    out_kernel<<<dim3(NROWS / 64, NB), 256>>>(key_cur, val_cur, out);
}

// round 4
// speedup vs baseline: 1.0362x; 1.0362x over previous
#include <cuda_runtime.h>

// Problem constants
#define NB       4
#define TOK      131072          // T*n tokens per batch
#define C        64
#define NROWS    16384           // n
#define SPLITS   128             // split-K blocks per batch
#define TPS      (TOK / SPLITS)  // 1024 tokens per block
#define NGROUPS  4               // split-K sub-groups within a block
#define TPG      (TPS / NGROUPS) // 256 tokens per sub-group
#define STAGE_T  8               // tokens per sub-group per stage
#define NSTAGES  (TPG / STAGE_T) // 32
#define NBUF     4               // kv pipeline depth
#define SROWS    (NGROUPS * STAGE_T)  // 32 rows per stage buffer
#define RP       68              // padded row length (floats)

#define KV_SMEM_BYTES  (NBUF * 2 * SROWS * RP * 4)          // 69,632
#define OUT_SMEM_BYTES (C * C * 4 + 2 * 64 * RP * 4)        // 51,200

// Scratch (no allocations allowed)
__device__ float g_partial[(size_t)NB * SPLITS * C * C];    // 8 MB partials [b][s][c][d]
__device__ float g_kv[NB * C * C];                          // [b][c][d]
__device__ float g_sm[NB * C * C];                          // [b][c][d], alpha folded in

typedef unsigned long long u64;

__device__ __forceinline__ u64 fma2(u64 a, u64 b, u64 c) {
    u64 d;
    asm("fma.rn.f32x2 %0, %1, %2, %3;" : "=l"(d) : "l"(a), "l"(b), "l"(c));
    return d;
}
__device__ __forceinline__ u64 add2(u64 a, u64 b) {
    u64 d;
    asm("add.rn.f32x2 %0, %1, %2;" : "=l"(d) : "l"(a), "l"(b));
    return d;
}
__device__ __forceinline__ u64 pack2(float x, float y) {
    u64 r;
    asm("mov.b64 %0, {%1, %2};" : "=l"(r) : "f"(x), "f"(y));
    return r;
}
__device__ __forceinline__ float2 unpack2(u64 v) {
    float2 r;
    asm("mov.b64 {%0, %1}, %2;" : "=f"(r.x), "=f"(r.y) : "l"(v));
    return r;
}

__device__ __forceinline__ void cp16(unsigned dst, const float* src) {
    asm volatile("cp.async.ca.shared.global [%0], [%1], 16;" :: "r"(dst), "l"(src));
}
__device__ __forceinline__ void cp_commit() {
    asm volatile("cp.async.commit_group;");
}
template <int N>
__device__ __forceinline__ void cp_wait() {
    asm volatile("cp.async.wait_group %0;" :: "n"(N));
}

// ---------------------------------------------------------------------------
// Kernel A: partial kv_mul. Round-2 inner loop (proven) + 4-deep cp.async
// pipeline with one __syncthreads per stage.
// 256 threads = 4 split-K sub-groups of 64; each sub-group's 8x8 thread grid
// covers the full 64x64 output with 8c x 8d register tiles (32 f32x2 accs).
// Pipeline invariant per iter it:  commits so far = s0..s_{it+2};
//   wait<2>  -> s_it complete for this thread
//   sync     -> s_it complete for ALL threads; all threads done computing it-1
//   prefetch s_{it+3} into buf (it+3)%4 == (it-1)%4  (free by the sync)
// ---------------------------------------------------------------------------
__global__ __launch_bounds__(256, 2) void kv_partial_kernel(
    const float* __restrict__ Kg, const float* __restrict__ Vg)
{
    extern __shared__ __align__(16) float s[];
    // s[((buf*2 + arr)*SROWS + row)*RP + col]
    const int BUFSTRIDE = 2 * SROWS * RP * 4;  // bytes per buffer (17,408)

    const int b   = blockIdx.y;
    const int sp  = blockIdx.x;
    const int tid = threadIdx.x;
    const int g   = tid >> 6;          // sub-group 0..3
    const int gt  = tid & 63;
    const int c0  = (gt >> 3) * 8;     // tile c origin
    const int d0  = (gt & 7) * 8;      // tile d origin

    // cp.async chunk mapping: 1024 16B-chunks per stage, 4 per thread
    const float* src[4];
    unsigned dstb[4];
    #pragma unroll
    for (int j = 0; j < 4; ++j) {
        int ch  = tid + j * 256;       // 0..1023
        int arr = ch >> 9;             // 0=K, 1=V
        int wi  = ch & 511;
        int row = wi >> 4;             // 0..31  (= group*8 + token-in-stage)
        int c4  = wi & 15;
        int gr  = row >> 3, tl = row & 7;
        size_t tok = (size_t)b * TOK + (size_t)sp * TPS + (size_t)gr * TPG + tl;
        src[j]  = (arr == 0 ? Kg : Vg) + tok * C + c4 * 4;
        dstb[j] = (unsigned)__cvta_generic_to_shared(
                      &s[((0 * 2 + arr) * SROWS + row) * RP + c4 * 4]);
    }

    // prologue: stages 0..2 into buffers 0..2 (stage advance = 8 tokens = 512 floats)
    #pragma unroll
    for (int st = 0; st < 3; ++st) {
        #pragma unroll
        for (int j = 0; j < 4; ++j)
            cp16(dstb[j] + st * BUFSTRIDE, src[j] + (size_t)st * 512);
        cp_commit();
    }

    u64 acc[4][8];   // [c-pair][d]
    #pragma unroll
    for (int i = 0; i < 4; ++i)
        #pragma unroll
        for (int d = 0; d < 8; ++d) acc[i][d] = 0ull;

    for (int it = 0; it < NSTAGES; ++it) {
        cp_wait<2>();
        __syncthreads();
        if (it + 3 < NSTAGES) {
            const int pbuf = (it + 3) & 3;
            #pragma unroll
            for (int j = 0; j < 4; ++j)
                cp16(dstb[j] + pbuf * BUFSTRIDE, src[j] + (size_t)(it + 3) * 512);
        }
        cp_commit();  // unconditional: keeps wait_group arithmetic valid at tail

        const int buf = it & 3;
        const float* kb_ = &s[((buf * 2 + 0) * SROWS) * RP];
        const float* vb_ = &s[((buf * 2 + 1) * SROWS) * RP];
        #pragma unroll
        for (int t = 0; t < STAGE_T; ++t) {
            const int r = g * STAGE_T + t;
            ulonglong2 ka = *(const ulonglong2*)&kb_[r * RP + c0];
            ulonglong2 kb = *(const ulonglong2*)&kb_[r * RP + c0 + 4];
            float4 va = *(const float4*)&vb_[r * RP + d0];
            float4 vb = *(const float4*)&vb_[r * RP + d0 + 4];
            u64 vd[8];
            vd[0] = pack2(va.x, va.x); vd[1] = pack2(va.y, va.y);
            vd[2] = pack2(va.z, va.z); vd[3] = pack2(va.w, va.w);
            vd[4] = pack2(vb.x, vb.x); vd[5] = pack2(vb.y, vb.y);
            vd[6] = pack2(vb.z, vb.z); vd[7] = pack2(vb.w, vb.w);
            #pragma unroll
            for (int d = 0; d < 8; ++d) {
                acc[0][d] = fma2(ka.x, vd[d], acc[0][d]);
                acc[1][d] = fma2(ka.y, vd[d], acc[1][d]);
                acc[2][d] = fma2(kb.x, vd[d], acc[2][d]);
                acc[3][d] = fma2(kb.y, vd[d], acc[3][d]);
            }
        }
    }

    // deterministic staged in-block split-K reduction (g0 += g1 += g2 += g3)
    __syncthreads();
    u64* sred = (u64*)s;   // 64 thr * 32 u64 = 16 KB
    #pragma unroll
    for (int rr = 1; rr < NGROUPS; ++rr) {
        if (g == rr) {
            u64* dst = &sred[gt * 32];
            #pragma unroll
            for (int i = 0; i < 4; ++i)
                #pragma unroll
                for (int d = 0; d < 8; ++d) dst[i * 8 + d] = acc[i][d];
        }
        __syncthreads();
        if (g == 0) {
            const u64* s2 = &sred[gt * 32];
            #pragma unroll
            for (int i = 0; i < 4; ++i)
                #pragma unroll
                for (int d = 0; d < 8; ++d) acc[i][d] = add2(acc[i][d], s2[i * 8 + d]);
        }
        __syncthreads();
    }

    if (g == 0) {
        float* outp = &g_partial[((size_t)(b * SPLITS + sp)) * (C * C)];
        #pragma unroll
        for (int i = 0; i < 4; ++i) {
            float2 u[8];
            #pragma unroll
            for (int d = 0; d < 8; ++d) u[d] = unpack2(acc[i][d]);
            *(float4*)&outp[(c0 + 2 * i) * C + d0]         = make_float4(u[0].x, u[1].x, u[2].x, u[3].x);
            *(float4*)&outp[(c0 + 2 * i) * C + d0 + 4]     = make_float4(u[4].x, u[5].x, u[6].x, u[7].x);
            *(float4*)&outp[(c0 + 2 * i + 1) * C + d0]     = make_float4(u[0].y, u[1].y, u[2].y, u[3].y);
            *(float4*)&outp[(c0 + 2 * i + 1) * C + d0 + 4] = make_float4(u[4].y, u[5].y, u[6].y, u[7].y);
        }
    }
}

// ---------------------------------------------------------------------------
// Kernel B: deterministic split reduction (float4, fixed order).
// ---------------------------------------------------------------------------
__global__ void kv_reduce_kernel()
{
    int q = blockIdx.x * 128 + threadIdx.x;   // 0..4095 float4 index
    int b  = q >> 10;
    int e4 = q & 1023;
    const float4* p = (const float4*)&g_partial[(size_t)b * SPLITS * (C * C)] + e4;
    float4 s0 = make_float4(0.f,0.f,0.f,0.f), s1 = s0, s2 = s0, s3 = s0;
    #pragma unroll 4
    for (int i = 0; i < SPLITS; i += 4) {
        float4 t0 = p[(size_t)(i    ) * 1024];
        float4 t1 = p[(size_t)(i + 1) * 1024];
        float4 t2 = p[(size_t)(i + 2) * 1024];
        float4 t3 = p[(size_t)(i + 3) * 1024];
        s0.x += t0.x; s0.y += t0.y; s0.z += t0.z; s0.w += t0.w;
        s1.x += t1.x; s1.y += t1.y; s1.z += t1.z; s1.w += t1.w;
        s2.x += t2.x; s2.y += t2.y; s2.z += t2.z; s2.w += t2.w;
        s3.x += t3.x; s3.y += t3.y; s3.z += t3.z; s3.w += t3.w;
    }
    float4 r;
    r.x = (s0.x + s1.x) + (s2.x + s3.x);
    r.y = (s0.y + s1.y) + (s2.y + s3.y);
    r.z = (s0.z + s1.z) + (s2.z + s3.z);
    r.w = (s0.w + s1.w) + (s2.w + s3.w);
    ((float4*)g_kv)[q] = r;
}

// ---------------------------------------------------------------------------
// Kernel C: softmax over the C axis (column-strided), alpha folded in.
// One thread per (b, d) column: 256 threads.
// ---------------------------------------------------------------------------
__global__ void softmax_kernel(const float* __restrict__ alpha)
{
    int tid = threadIdx.x;
    int b = tid >> 6;
    int d = tid & 63;
    const float* in  = &g_kv[b * (C * C) + d];
    float*       out = &g_sm[b * (C * C) + d];

    float v[C];
    float m = -3.402823466e38f;
    #pragma unroll
    for (int c = 0; c < C; ++c) { v[c] = in[c * C]; m = fmaxf(m, v[c]); }
    float sum = 0.f;
    #pragma unroll
    for (int c = 0; c < C; ++c) { v[c] = expf(v[c] - m); sum += v[c]; }
    float sc = alpha[0] / sum;
    #pragma unroll
    for (int c = 0; c < C; ++c) out[c * C] = v[c] * sc;
}

// ---------------------------------------------------------------------------
// Kernel D: out[b,r,d] = sum_c key_cur[b,r,c] * sm[b,c,d] + val_cur.
// 256 threads, 256 rows per block (4 sub-tiles of 64 rows, cp.async
// double-buffered), sm matrix (alpha folded) loaded once per block.
// Thread = 2 rows x 8 d; conflict-free broadcast sm loads (row-major s_sm).
// ---------------------------------------------------------------------------
__global__ __launch_bounds__(256, 2) void out_kernel(
    const float* __restrict__ key_cur, const float* __restrict__ val_cur,
    float* __restrict__ out)
{
    extern __shared__ __align__(16) float s[];
    float* s_sm  = s;                 // [c][d] 64x64, 16 KB
    float* s_key = s + C * C;         // [2][64][RP]
    const int KEYBUF = 64 * RP;       // floats per key buffer

    const int b   = blockIdx.y;
    const int rb  = blockIdx.x;       // 0..63 (256 rows each)
    const int tid = threadIdx.x;
    const size_t row_base = (size_t)b * NROWS + (size_t)rb * 256;

    // key tile chunk mapping: 64 rows x 16 chunks = 1024, 4 per thread
    const float* ksrc[4];
    unsigned kdst[4];
    #pragma unroll
    for (int j = 0; j < 4; ++j) {
        int ch  = tid + j * 256;
        int row = ch >> 4, c4 = ch & 15;
        ksrc[j] = key_cur + (row_base + row) * C + c4 * 4;
        kdst[j] = (unsigned)__cvta_generic_to_shared(&s_key[row * RP + c4 * 4]);
    }

    // prologue: key sub-tile 0 -> buf 0 ; sm matrix via LDG/STS
    #pragma unroll
    for (int j = 0; j < 4; ++j) cp16(kdst[j], ksrc[j]);
    cp_commit();
    const float* smg = &g_sm[b * (C * C)];
    #pragma unroll
    for (int j = 0; j < 4; ++j) {
        int q = j * 256 + tid;
        *(float4*)&s_sm[q * 4] = *(const float4*)&smg[q * 4];
    }

    const int rg = tid >> 3;          // 0..31
    const int dg = tid & 7;           // 0..7
    const int r0 = rg * 2, d0 = dg * 8;

    for (int rt = 0; rt < 4; ++rt) {
        __syncthreads();              // prev compute done -> buf (rt+1)&1 free; sm ready
        if (rt + 1 < 4) {
            const int pb = (rt + 1) & 1;
            #pragma unroll
            for (int j = 0; j < 4; ++j)
                cp16(kdst[j] + pb * KEYBUF * 4, ksrc[j] + (size_t)(rt + 1) * 64 * C);
        }
        cp_commit();
        cp_wait<1>();
        __syncthreads();

        const float* kt = &s_key[(rt & 1) * KEYBUF];
        u64 acc[2][4];
        #pragma unroll
        for (int i = 0; i < 2; ++i)
            #pragma unroll
            for (int p = 0; p < 4; ++p) acc[i][p] = 0ull;

        #pragma unroll 4
        for (int cq = 0; cq < 16; ++cq) {
            float4 k0 = *(const float4*)&kt[(r0    ) * RP + cq * 4];
            float4 k1 = *(const float4*)&kt[(r0 + 1) * RP + cq * 4];
            float kk[2][4] = {{k0.x, k0.y, k0.z, k0.w}, {k1.x, k1.y, k1.z, k1.w}};
            #pragma unroll
            for (int cc = 0; cc < 4; ++cc) {
                ulonglong2 sa = *(const ulonglong2*)&s_sm[(cq * 4 + cc) * C + d0];
                ulonglong2 sb = *(const ulonglong2*)&s_sm[(cq * 4 + cc) * C + d0 + 4];
                #pragma unroll
                for (int i = 0; i < 2; ++i) {
                    u64 kd = pack2(kk[i][cc], kk[i][cc]);
                    acc[i][0] = fma2(kd, sa.x, acc[i][0]);
                    acc[i][1] = fma2(kd, sa.y, acc[i][1]);
                    acc[i][2] = fma2(kd, sb.x, acc[i][2]);
                    acc[i][3] = fma2(kd, sb.y, acc[i][3]);
                }
            }
        }

        #pragma unroll
        for (int i = 0; i < 2; ++i) {
            size_t base = (row_base + rt * 64 + r0 + i) * C + d0;
            float4 v0 = *(const float4*)&val_cur[base];
            float4 v1 = *(const float4*)&val_cur[base + 4];
            float2 p0 = unpack2(acc[i][0]), p1 = unpack2(acc[i][1]);
            float2 p2 = unpack2(acc[i][2]), p3 = unpack2(acc[i][3]);
            *(float4*)&out[base]     = make_float4(p0.x + v0.x, p0.y + v0.y,
                                                   p1.x + v0.z, p1.y + v0.w);
            *(float4*)&out[base + 4] = make_float4(p2.x + v1.x, p2.y + v1.y,
                                                   p3.x + v1.z, p3.y + v1.w);
        }
    }
}

// ---------------------------------------------------------------------------
extern "C" void kernel_launch(void* const* d_in, const int* in_sizes, int n_in,
                              void* d_out, int out_size)
{
    const float* key_mem = (const float*)d_in[0];
    const float* val_mem = (const float*)d_in[1];
    const float* key_cur = (const float*)d_in[2];
    const float* val_cur = (const float*)d_in[3];
    const float* alpha   = (const float*)d_in[4];
    float* out = (float*)d_out;

    cudaFuncSetAttribute(kv_partial_kernel,
                         cudaFuncAttributeMaxDynamicSharedMemorySize, KV_SMEM_BYTES);
    cudaFuncSetAttribute(out_kernel,
                         cudaFuncAttributeMaxDynamicSharedMemorySize, OUT_SMEM_BYTES);

    kv_partial_kernel<<<dim3(SPLITS, NB), 256, KV_SMEM_BYTES>>>(key_mem, val_mem);
    kv_reduce_kernel<<<32, 128>>>();
    softmax_kernel<<<1, 256>>>(alpha);
    out_kernel<<<dim3(NROWS / 256, NB), 256, OUT_SMEM_BYTES>>>(key_cur, val_cur, out);
}

// round 5
// speedup vs baseline: 1.1502x; 1.1100x over previous
#include <cuda_runtime.h>

// Problem constants
#define NB       4
#define TOK      131072          // T*n tokens per batch
#define C        64
#define NROWS    16384           // n
#define SPLITS   128             // split-K blocks per batch
#define TPS      (TOK / SPLITS)  // 1024 tokens per block
#define NGROUPS  4               // split-K sub-groups within a block
#define TPG      (TPS / NGROUPS) // 256 tokens per sub-group
#define STAGE_T  16              // tokens per sub-group per stage
#define NSTAGES  (TPG / STAGE_T) // 16
#define SROWS    (NGROUPS * STAGE_T)  // 64 rows per stage buffer
#define RP       68              // padded row length (floats)

#define KV_SMEM_BYTES  (2 * 2 * SROWS * RP * 4)             // 69,632
#define OUT_SMEM_BYTES ((C * C + 128 * RP) * 4)             // 51,200

// Scratch (no allocations allowed)
__device__ float g_partial[(size_t)NB * SPLITS * C * C];    // 8 MB partials [b][s][c][d]
__device__ float g_kv[NB * C * C];                          // [b][c][d]
__device__ float g_sm[NB * C * C];                          // [b][c][d], alpha folded in

typedef unsigned long long u64;

__device__ __forceinline__ u64 fma2(u64 a, u64 b, u64 c) {
    u64 d;
    asm("fma.rn.f32x2 %0, %1, %2, %3;" : "=l"(d) : "l"(a), "l"(b), "l"(c));
    return d;
}
__device__ __forceinline__ u64 add2(u64 a, u64 b) {
    u64 d;
    asm("add.rn.f32x2 %0, %1, %2;" : "=l"(d) : "l"(a), "l"(b));
    return d;
}
__device__ __forceinline__ u64 pack2(float x, float y) {
    u64 r;
    asm("mov.b64 %0, {%1, %2};" : "=l"(r) : "f"(x), "f"(y));
    return r;
}
__device__ __forceinline__ float2 unpack2(u64 v) {
    float2 r;
    asm("mov.b64 {%0, %1}, %2;" : "=f"(r.x), "=f"(r.y) : "l"(v));
    return r;
}

// ---------------------------------------------------------------------------
// Kernel A: partial kv_mul. LDG.128 -> regs -> STS.128 double buffering
// (cp.async removed: LDGSTS issue rate of 16B/8cyc/SMSP caps the chip at
// ~2.2 TB/s, which was the round-2..4 wall).
// 256 threads = 4 split-K sub-groups of 64; each sub-group's 8x8 thread grid
// covers the full 64x64 output with 8c x 8d register tiles (32 f32x2 accs),
// accumulating over its private 256 tokens in 16-token stages.
// Per stage: STS(regs for s_{it+1}) -> LDG(regs for s_{it+2}) -> compute s_it
// -> barrier. LDG lead time = one full stage of compute (>1000 cyc).
// ---------------------------------------------------------------------------
__global__ __launch_bounds__(256, 2) void kv_partial_kernel(
    const float* __restrict__ Kg, const float* __restrict__ Vg)
{
    extern __shared__ __align__(16) float s[];
    // layout: s[((buf*2 + arr)*SROWS + row)*RP + col]
    const int BUFW = 2 * SROWS * RP;       // floats per buffer

    const int b   = blockIdx.y;
    const int sp  = blockIdx.x;
    const int tid = threadIdx.x;
    const int g   = tid >> 6;              // sub-group 0..3
    const int gt  = tid & 63;
    const int c0  = (gt >> 3) * 8;         // tile c origin
    const int d0  = (gt & 7) * 8;          // tile d origin

    // Chunk mapping: 2048 16B-chunks per stage (2 arrays x 64 rows x 16).
    // Chunks j=0..3 -> K array, j=4..7 -> V array at the SAME (row,c4):
    //   ch = tid + j*256 for K;  V repeats the pattern.
    int offw[4];    // float offset within the array for stage 0
    int dstw[4];    // float offset within a (buf,arr) smem plane
    #pragma unroll
    for (int j = 0; j < 4; ++j) {
        int ch  = tid + j * 256;           // 0..1023
        int row = ch >> 4;                 // 0..63  (= group*16 + token)
        int c4  = ch & 15;
        int gr  = row >> 4, tl = row & 15;
        offw[j] = (gr * TPG + tl) * C + c4 * 4;
        dstw[j] = row * RP + c4 * 4;
    }
    const float* Kbase = Kg + ((size_t)b * TOK + (size_t)sp * TPS) * C;
    const float* Vbase = Vg + ((size_t)b * TOK + (size_t)sp * TPS) * C;

    float4 pf[8];
    // prologue: stage 0 -> regs -> buf0 ; stage 1 -> regs
    #pragma unroll
    for (int j = 0; j < 4; ++j) {
        pf[j]     = *(const float4*)(Kbase + offw[j]);
        pf[j + 4] = *(const float4*)(Vbase + offw[j]);
    }
    #pragma unroll
    for (int j = 0; j < 4; ++j) {
        *(float4*)&s[dstw[j]]             = pf[j];
        *(float4*)&s[SROWS * RP + dstw[j]] = pf[j + 4];
    }
    #pragma unroll
    for (int j = 0; j < 4; ++j) {
        pf[j]     = *(const float4*)(Kbase + offw[j] + STAGE_T * C);
        pf[j + 4] = *(const float4*)(Vbase + offw[j] + STAGE_T * C);
    }
    __syncthreads();

    u64 acc[4][8];   // [c-pair][d]
    #pragma unroll
    for (int i = 0; i < 4; ++i)
        #pragma unroll
        for (int d = 0; d < 8; ++d) acc[i][d] = 0ull;

    #pragma unroll 1
    for (int it = 0; it < NSTAGES; ++it) {
        // stash stage it+1 (in regs) into the buffer freed by stage it-1
        if (it + 1 < NSTAGES) {
            float* dstB = &s[((it + 1) & 1) * BUFW];
            #pragma unroll
            for (int j = 0; j < 4; ++j) {
                *(float4*)&dstB[dstw[j]]              = pf[j];
                *(float4*)&dstB[SROWS * RP + dstw[j]] = pf[j + 4];
            }
        }
        // prefetch stage it+2 into regs (consumed next iteration)
        if (it + 2 < NSTAGES) {
            const int adv = (it + 2) * STAGE_T * C;
            #pragma unroll
            for (int j = 0; j < 4; ++j) {
                pf[j]     = *(const float4*)(Kbase + offw[j] + adv);
                pf[j + 4] = *(const float4*)(Vbase + offw[j] + adv);
            }
        }

        const float* kb_ = &s[(it & 1) * BUFW];
        const float* vb_ = kb_ + SROWS * RP;
        #pragma unroll
        for (int t = 0; t < STAGE_T; ++t) {
            const int r = g * STAGE_T + t;
            ulonglong2 ka = *(const ulonglong2*)&kb_[r * RP + c0];
            ulonglong2 kb = *(const ulonglong2*)&kb_[r * RP + c0 + 4];
            float4 va = *(const float4*)&vb_[r * RP + d0];
            float4 vb = *(const float4*)&vb_[r * RP + d0 + 4];
            u64 vd[8];
            vd[0] = pack2(va.x, va.x); vd[1] = pack2(va.y, va.y);
            vd[2] = pack2(va.z, va.z); vd[3] = pack2(va.w, va.w);
            vd[4] = pack2(vb.x, vb.x); vd[5] = pack2(vb.y, vb.y);
            vd[6] = pack2(vb.z, vb.z); vd[7] = pack2(vb.w, vb.w);
            #pragma unroll
            for (int d = 0; d < 8; ++d) {
                acc[0][d] = fma2(ka.x, vd[d], acc[0][d]);
                acc[1][d] = fma2(ka.y, vd[d], acc[1][d]);
                acc[2][d] = fma2(kb.x, vd[d], acc[2][d]);
                acc[3][d] = fma2(kb.y, vd[d], acc[3][d]);
            }
        }
        __syncthreads();   // compute of it done everywhere; STS of it+1 drained
    }

    // deterministic staged in-block split-K reduction (g0 += g1 += g2 += g3)
    u64* sred = (u64*)s;   // 64 thr * 32 u64 = 16 KB
    #pragma unroll
    for (int rr = 1; rr < NGROUPS; ++rr) {
        if (g == rr) {
            u64* dst = &sred[gt * 32];
            #pragma unroll
            for (int i = 0; i < 4; ++i)
                #pragma unroll
                for (int d = 0; d < 8; ++d) dst[i * 8 + d] = acc[i][d];
        }
        __syncthreads();
        if (g == 0) {
            const u64* s2 = &sred[gt * 32];
            #pragma unroll
            for (int i = 0; i < 4; ++i)
                #pragma unroll
                for (int d = 0; d < 8; ++d) acc[i][d] = add2(acc[i][d], s2[i * 8 + d]);
        }
        __syncthreads();
    }

    if (g == 0) {
        float* outp = &g_partial[((size_t)(b * SPLITS + sp)) * (C * C)];
        #pragma unroll
        for (int i = 0; i < 4; ++i) {
            float2 u[8];
            #pragma unroll
            for (int d = 0; d < 8; ++d) u[d] = unpack2(acc[i][d]);
            *(float4*)&outp[(c0 + 2 * i) * C + d0]         = make_float4(u[0].x, u[1].x, u[2].x, u[3].x);
            *(float4*)&outp[(c0 + 2 * i) * C + d0 + 4]     = make_float4(u[4].x, u[5].x, u[6].x, u[7].x);
            *(float4*)&outp[(c0 + 2 * i + 1) * C + d0]     = make_float4(u[0].y, u[1].y, u[2].y, u[3].y);
            *(float4*)&outp[(c0 + 2 * i + 1) * C + d0 + 4] = make_float4(u[4].y, u[5].y, u[6].y, u[7].y);
        }
    }
}

// ---------------------------------------------------------------------------
// Kernel B: deterministic split reduction (float4, fixed order).
// ---------------------------------------------------------------------------
__global__ void kv_reduce_kernel()
{
    int q = blockIdx.x * 128 + threadIdx.x;   // 0..4095 float4 index
    int b  = q >> 10;
    int e4 = q & 1023;
    const float4* p = (const float4*)&g_partial[(size_t)b * SPLITS * (C * C)] + e4;
    float4 s0 = make_float4(0.f,0.f,0.f,0.f), s1 = s0, s2 = s0, s3 = s0;
    float4 s4 = s0, s5 = s0, s6 = s0, s7 = s0;
    #pragma unroll 2
    for (int i = 0; i < SPLITS; i += 8) {
        float4 t0 = p[(size_t)(i    ) * 1024];
        float4 t1 = p[(size_t)(i + 1) * 1024];
        float4 t2 = p[(size_t)(i + 2) * 1024];
        float4 t3 = p[(size_t)(i + 3) * 1024];
        float4 t4 = p[(size_t)(i + 4) * 1024];
        float4 t5 = p[(size_t)(i + 5) * 1024];
        float4 t6 = p[(size_t)(i + 6) * 1024];
        float4 t7 = p[(size_t)(i + 7) * 1024];
        s0.x += t0.x; s0.y += t0.y; s0.z += t0.z; s0.w += t0.w;
        s1.x += t1.x; s1.y += t1.y; s1.z += t1.z; s1.w += t1.w;
        s2.x += t2.x; s2.y += t2.y; s2.z += t2.z; s2.w += t2.w;
        s3.x += t3.x; s3.y += t3.y; s3.z += t3.z; s3.w += t3.w;
        s4.x += t4.x; s4.y += t4.y; s4.z += t4.z; s4.w += t4.w;
        s5.x += t5.x; s5.y += t5.y; s5.z += t5.z; s5.w += t5.w;
        s6.x += t6.x; s6.y += t6.y; s6.z += t6.z; s6.w += t6.w;
        s7.x += t7.x; s7.y += t7.y; s7.z += t7.z; s7.w += t7.w;
    }
    float4 r;
    r.x = ((s0.x + s1.x) + (s2.x + s3.x)) + ((s4.x + s5.x) + (s6.x + s7.x));
    r.y = ((s0.y + s1.y) + (s2.y + s3.y)) + ((s4.y + s5.y) + (s6.y + s7.y));
    r.z = ((s0.z + s1.z) + (s2.z + s3.z)) + ((s4.z + s5.z) + (s6.z + s7.z));
    r.w = ((s0.w + s1.w) + (s2.w + s3.w)) + ((s4.w + s5.w) + (s6.w + s7.w));
    ((float4*)g_kv)[q] = r;
}

// ---------------------------------------------------------------------------
// Kernel C: softmax over the C axis (column-strided), alpha folded in.
// ---------------------------------------------------------------------------
__global__ void softmax_kernel(const float* __restrict__ alpha)
{
    int tid = threadIdx.x;
    int b = tid >> 6;
    int d = tid & 63;
    const float* in  = &g_kv[b * (C * C) + d];
    float*       out = &g_sm[b * (C * C) + d];

    float v[C];
    float m = -3.402823466e38f;
    #pragma unroll
    for (int c = 0; c < C; ++c) { v[c] = in[c * C]; m = fmaxf(m, v[c]); }
    float sum = 0.f;
    #pragma unroll
    for (int c = 0; c < C; ++c) { v[c] = expf(v[c] - m); sum += v[c]; }
    float sc = alpha[0] / sum;
    #pragma unroll
    for (int c = 0; c < C; ++c) out[c * C] = v[c] * sc;
}

// ---------------------------------------------------------------------------
// Kernel D: out[b,r,d] = sum_c key_cur[b,r,c] * sm[b,c,d] + val_cur.
// 128 threads, 128 rows per block; thread = 8 rows (strided by 16) x 8 d
// (32 f32x2 accs). Strided rows keep the 4 distinct key-LDS addresses per
// warp in different banks (rg*68 = 4*rg mod 32). sm loads are broadcast.
// ---------------------------------------------------------------------------
__global__ __launch_bounds__(128, 4) void out_kernel(
    const float* __restrict__ key_cur, const float* __restrict__ val_cur,
    float* __restrict__ out)
{
    extern __shared__ __align__(16) float s[];
    float* s_sm  = s;                 // [c][d] 64x64, 16 KB
    float* s_key = s + C * C;         // [128][RP]

    const int b   = blockIdx.y;
    const int rb  = blockIdx.x;       // 0..127 (128 rows each)
    const int tid = threadIdx.x;
    const size_t row_base = (size_t)b * NROWS + (size_t)rb * 128;

    // sm matrix (alpha folded): 1024 float4 / 128 thr = 8 each
    const float* smg = &g_sm[b * (C * C)];
    #pragma unroll
    for (int j = 0; j < 8; ++j) {
        int q = j * 128 + tid;
        *(float4*)&s_sm[q * 4] = *(const float4*)&smg[q * 4];
    }
    // keys: 128 rows x 16 chunks = 2048 float4 / 128 thr = 16 each
    #pragma unroll
    for (int j = 0; j < 16; ++j) {
        int ch  = j * 128 + tid;
        int row = ch >> 4, c4 = ch & 15;
        *(float4*)&s_key[row * RP + c4 * 4] =
            *(const float4*)&key_cur[(row_base + row) * C + c4 * 4];
    }
    __syncthreads();

    const int rg = tid >> 3;          // 0..15: rows rg, rg+16, ..., rg+112
    const int d0 = (tid & 7) * 8;

    u64 acc[8][4];
    #pragma unroll
    for (int i = 0; i < 8; ++i)
        #pragma unroll
        for (int p = 0; p < 4; ++p) acc[i][p] = 0ull;

    #pragma unroll 2
    for (int cq = 0; cq < 16; ++cq) {
        float4 kq[8];
        #pragma unroll
        for (int i = 0; i < 8; ++i)
            kq[i] = *(const float4*)&s_key[(rg + 16 * i) * RP + cq * 4];
        #pragma unroll
        for (int cc = 0; cc < 4; ++cc) {
            ulonglong2 sa = *(const ulonglong2*)&s_sm[(cq * 4 + cc) * C + d0];
            ulonglong2 sb = *(const ulonglong2*)&s_sm[(cq * 4 + cc) * C + d0 + 4];
            #pragma unroll
            for (int i = 0; i < 8; ++i) {
                float kc = (cc == 0) ? kq[i].x : (cc == 1) ? kq[i].y
                         : (cc == 2) ? kq[i].z : kq[i].w;
                u64 kd = pack2(kc, kc);
                acc[i][0] = fma2(kd, sa.x, acc[i][0]);
                acc[i][1] = fma2(kd, sa.y, acc[i][1]);
                acc[i][2] = fma2(kd, sb.x, acc[i][2]);
                acc[i][3] = fma2(kd, sb.y, acc[i][3]);
            }
        }
    }

    #pragma unroll
    for (int i = 0; i < 8; ++i) {
        size_t base = (row_base + rg + 16 * i) * C + d0;
        float4 v0 = *(const float4*)&val_cur[base];
        float4 v1 = *(const float4*)&val_cur[base + 4];
        float2 p0 = unpack2(acc[i][0]), p1 = unpack2(acc[i][1]);
        float2 p2 = unpack2(acc[i][2]), p3 = unpack2(acc[i][3]);
        *(float4*)&out[base]     = make_float4(p0.x + v0.x, p0.y + v0.y,
                                               p1.x + v0.z, p1.y + v0.w);
        *(float4*)&out[base + 4] = make_float4(p2.x + v1.x, p2.y + v1.y,
                                               p3.x + v1.z, p3.y + v1.w);
    }
}

// ---------------------------------------------------------------------------
extern "C" void kernel_launch(void* const* d_in, const int* in_sizes, int n_in,
                              void* d_out, int out_size)
{
    const float* key_mem = (const float*)d_in[0];
    const float* val_mem = (const float*)d_in[1];
    const float* key_cur = (const float*)d_in[2];
    const float* val_cur = (const float*)d_in[3];
    const float* alpha   = (const float*)d_in[4];
    float* out = (float*)d_out;

    cudaFuncSetAttribute(kv_partial_kernel,
                         cudaFuncAttributeMaxDynamicSharedMemorySize, KV_SMEM_BYTES);
    cudaFuncSetAttribute(out_kernel,
                         cudaFuncAttributeMaxDynamicSharedMemorySize, OUT_SMEM_BYTES);

    kv_partial_kernel<<<dim3(SPLITS, NB), 256, KV_SMEM_BYTES>>>(key_mem, val_mem);
    kv_reduce_kernel<<<32, 128>>>();
    softmax_kernel<<<1, 256>>>(alpha);
    out_kernel<<<dim3(NROWS / 128, NB), 128, OUT_SMEM_BYTES>>>(key_cur, val_cur, out);
}

// round 6
// speedup vs baseline: 1.1797x; 1.0256x over previous
#include <cuda_runtime.h>

// Problem constants
#define NB       4
#define TOK      131072          // T*n tokens per batch
#define C        64
#define NROWS    16384           // n
#define SPLITS   128             // split-K blocks per batch
#define TPS      (TOK / SPLITS)  // 1024 tokens per block
#define NGROUPS  4               // split-K sub-groups within a block
#define TPG      (TPS / NGROUPS) // 256 tokens per sub-group
#define STAGE_T  16              // tokens per sub-group per stage
#define NSTAGES  (TPG / STAGE_T) // 16
#define SROWS    (NGROUPS * STAGE_T)  // 64 rows per stage buffer
#define RP       68              // padded row length (floats)

#define KV_SMEM_BYTES  (2 * 2 * SROWS * RP * 4)             // 69,632
#define OUT_SMEM_BYTES ((C * C + 128 * RP) * 4)             // 51,200

// Scratch (no allocations allowed)
__device__ float g_partial[(size_t)NB * SPLITS * C * C];    // 8 MB partials [b][s][c][d]
__device__ float g_kv[NB * C * C];                          // [b][c][d]
__device__ float g_sm[NB * C * C];                          // [b][c][d], alpha folded in

typedef unsigned long long u64;

__device__ __forceinline__ u64 fma2(u64 a, u64 b, u64 c) {
    u64 d;
    asm("fma.rn.f32x2 %0, %1, %2, %3;" : "=l"(d) : "l"(a), "l"(b), "l"(c));
    return d;
}
__device__ __forceinline__ u64 add2(u64 a, u64 b) {
    u64 d;
    asm("add.rn.f32x2 %0, %1, %2;" : "=l"(d) : "l"(a), "l"(b));
    return d;
}
__device__ __forceinline__ u64 pack2(float x, float y) {
    u64 r;
    asm("mov.b64 %0, {%1, %2};" : "=l"(r) : "f"(x), "f"(y));
    return r;
}
__device__ __forceinline__ float2 unpack2(u64 v) {
    float2 r;
    asm("mov.b64 {%0, %1}, %2;" : "=f"(r.x), "=f"(r.y) : "l"(v));
    return r;
}
__device__ __forceinline__ void stcg4(float* p, float4 v) {
    asm volatile("st.global.cg.v4.f32 [%0], {%1,%2,%3,%4};"
                 :: "l"(p), "f"(v.x), "f"(v.y), "f"(v.z), "f"(v.w));
}

// ---------------------------------------------------------------------------
// Kernel A: partial kv_mul. LDG.128 -> regs -> STS.128 double buffering.
// __launch_bounds__(256,1): 255-reg cap. The ~150-reg working set (64 acc +
// 32 prefetch + temps) previously spilled to local memory under the 128-reg
// cap of (256,2) — the invariant wall of rounds 2-5.
// 256 threads = 4 split-K sub-groups of 64; each sub-group's 8x8 thread grid
// covers the full 64x64 output with 8c x 8d register tiles (32 f32x2 accs).
// ---------------------------------------------------------------------------
__global__ __launch_bounds__(256, 1) void kv_partial_kernel(
    const float* __restrict__ Kg, const float* __restrict__ Vg)
{
    extern __shared__ __align__(16) float s[];
    const int BUFW = 2 * SROWS * RP;       // floats per buffer

    const int b   = blockIdx.y;
    const int sp  = blockIdx.x;
    const int tid = threadIdx.x;
    const int g   = tid >> 6;              // sub-group 0..3
    const int gt  = tid & 63;
    const int c0  = (gt >> 3) * 8;         // tile c origin
    const int d0  = (gt & 7) * 8;          // tile d origin

    int offw[4];    // float offset within the array for stage 0
    int dstw[4];    // float offset within a (buf,arr) smem plane
    #pragma unroll
    for (int j = 0; j < 4; ++j) {
        int ch  = tid + j * 256;           // 0..1023
        int row = ch >> 4;                 // 0..63  (= group*16 + token)
        int c4  = ch & 15;
        int gr  = row >> 4, tl = row & 15;
        offw[j] = (gr * TPG + tl) * C + c4 * 4;
        dstw[j] = row * RP + c4 * 4;
    }
    const float* Kbase = Kg + ((size_t)b * TOK + (size_t)sp * TPS) * C;
    const float* Vbase = Vg + ((size_t)b * TOK + (size_t)sp * TPS) * C;

    float4 pf[8];
    // prologue: stage 0 -> regs -> buf0 ; stage 1 -> regs
    #pragma unroll
    for (int j = 0; j < 4; ++j) {
        pf[j]     = *(const float4*)(Kbase + offw[j]);
        pf[j + 4] = *(const float4*)(Vbase + offw[j]);
    }
    #pragma unroll
    for (int j = 0; j < 4; ++j) {
        *(float4*)&s[dstw[j]]              = pf[j];
        *(float4*)&s[SROWS * RP + dstw[j]] = pf[j + 4];
    }
    #pragma unroll
    for (int j = 0; j < 4; ++j) {
        pf[j]     = *(const float4*)(Kbase + offw[j] + STAGE_T * C);
        pf[j + 4] = *(const float4*)(Vbase + offw[j] + STAGE_T * C);
    }
    __syncthreads();

    u64 acc[4][8];   // [c-pair][d]
    #pragma unroll
    for (int i = 0; i < 4; ++i)
        #pragma unroll
        for (int d = 0; d < 8; ++d) acc[i][d] = 0ull;

    #pragma unroll 1
    for (int it = 0; it < NSTAGES; ++it) {
        // stash stage it+1 (in regs) into the buffer freed by stage it-1
        if (it + 1 < NSTAGES) {
            float* dstB = &s[((it + 1) & 1) * BUFW];
            #pragma unroll
            for (int j = 0; j < 4; ++j) {
                *(float4*)&dstB[dstw[j]]              = pf[j];
                *(float4*)&dstB[SROWS * RP + dstw[j]] = pf[j + 4];
            }
        }
        // prefetch stage it+2 into regs (consumed next iteration)
        if (it + 2 < NSTAGES) {
            const int adv = (it + 2) * STAGE_T * C;
            #pragma unroll
            for (int j = 0; j < 4; ++j) {
                pf[j]     = *(const float4*)(Kbase + offw[j] + adv);
                pf[j + 4] = *(const float4*)(Vbase + offw[j] + adv);
            }
        }

        const float* kb_ = &s[(it & 1) * BUFW];
        const float* vb_ = kb_ + SROWS * RP;
        #pragma unroll
        for (int t = 0; t < STAGE_T; ++t) {
            const int r = g * STAGE_T + t;
            ulonglong2 ka = *(const ulonglong2*)&kb_[r * RP + c0];
            ulonglong2 kb = *(const ulonglong2*)&kb_[r * RP + c0 + 4];
            float4 va = *(const float4*)&vb_[r * RP + d0];
            float4 vb = *(const float4*)&vb_[r * RP + d0 + 4];
            u64 vd[8];
            vd[0] = pack2(va.x, va.x); vd[1] = pack2(va.y, va.y);
            vd[2] = pack2(va.z, va.z); vd[3] = pack2(va.w, va.w);
            vd[4] = pack2(vb.x, vb.x); vd[5] = pack2(vb.y, vb.y);
            vd[6] = pack2(vb.z, vb.z); vd[7] = pack2(vb.w, vb.w);
            #pragma unroll
            for (int d = 0; d < 8; ++d) {
                acc[0][d] = fma2(ka.x, vd[d], acc[0][d]);
                acc[1][d] = fma2(ka.y, vd[d], acc[1][d]);
                acc[2][d] = fma2(kb.x, vd[d], acc[2][d]);
                acc[3][d] = fma2(kb.y, vd[d], acc[3][d]);
            }
        }
        __syncthreads();   // compute of it done everywhere; STS of it+1 drained
    }

    // deterministic staged in-block split-K reduction (g0 += g1 += g2 += g3)
    u64* sred = (u64*)s;   // 64 thr * 32 u64 = 16 KB
    #pragma unroll
    for (int rr = 1; rr < NGROUPS; ++rr) {
        if (g == rr) {
            u64* dst = &sred[gt * 32];
            #pragma unroll
            for (int i = 0; i < 4; ++i)
                #pragma unroll
                for (int d = 0; d < 8; ++d) dst[i * 8 + d] = acc[i][d];
        }
        __syncthreads();
        if (g == 0) {
            const u64* s2 = &sred[gt * 32];
            #pragma unroll
            for (int i = 0; i < 4; ++i)
                #pragma unroll
                for (int d = 0; d < 8; ++d) acc[i][d] = add2(acc[i][d], s2[i * 8 + d]);
        }
        __syncthreads();
    }

    if (g == 0) {
        float* outp = &g_partial[((size_t)(b * SPLITS + sp)) * (C * C)];
        #pragma unroll
        for (int i = 0; i < 4; ++i) {
            float2 u[8];
            #pragma unroll
            for (int d = 0; d < 8; ++d) u[d] = unpack2(acc[i][d]);
            stcg4(&outp[(c0 + 2 * i) * C + d0],
                  make_float4(u[0].x, u[1].x, u[2].x, u[3].x));
            stcg4(&outp[(c0 + 2 * i) * C + d0 + 4],
                  make_float4(u[4].x, u[5].x, u[6].x, u[7].x));
            stcg4(&outp[(c0 + 2 * i + 1) * C + d0],
                  make_float4(u[0].y, u[1].y, u[2].y, u[3].y));
            stcg4(&outp[(c0 + 2 * i + 1) * C + d0 + 4],
                  make_float4(u[4].y, u[5].y, u[6].y, u[7].y));
        }
    }
}

// ---------------------------------------------------------------------------
// Kernel B: deterministic split reduction (float4, fixed order).
// ---------------------------------------------------------------------------
__global__ __launch_bounds__(128, 1) void kv_reduce_kernel()
{
    int q = blockIdx.x * 128 + threadIdx.x;   // 0..4095 float4 index
    int b  = q >> 10;
    int e4 = q & 1023;
    const float4* p = (const float4*)&g_partial[(size_t)b * SPLITS * (C * C)] + e4;
    float4 s0 = make_float4(0.f,0.f,0.f,0.f), s1 = s0, s2 = s0, s3 = s0;
    float4 s4 = s0, s5 = s0, s6 = s0, s7 = s0;
    #pragma unroll 2
    for (int i = 0; i < SPLITS; i += 8) {
        float4 t0 = p[(size_t)(i    ) * 1024];
        float4 t1 = p[(size_t)(i + 1) * 1024];
        float4 t2 = p[(size_t)(i + 2) * 1024];
        float4 t3 = p[(size_t)(i + 3) * 1024];
        float4 t4 = p[(size_t)(i + 4) * 1024];
        float4 t5 = p[(size_t)(i + 5) * 1024];
        float4 t6 = p[(size_t)(i + 6) * 1024];
        float4 t7 = p[(size_t)(i + 7) * 1024];
        s0.x += t0.x; s0.y += t0.y; s0.z += t0.z; s0.w += t0.w;
        s1.x += t1.x; s1.y += t1.y; s1.z += t1.z; s1.w += t1.w;
        s2.x += t2.x; s2.y += t2.y; s2.z += t2.z; s2.w += t2.w;
        s3.x += t3.x; s3.y += t3.y; s3.z += t3.z; s3.w += t3.w;
        s4.x += t4.x; s4.y += t4.y; s4.z += t4.z; s4.w += t4.w;
        s5.x += t5.x; s5.y += t5.y; s5.z += t5.z; s5.w += t5.w;
        s6.x += t6.x; s6.y += t6.y; s6.z += t6.z; s6.w += t6.w;
        s7.x += t7.x; s7.y += t7.y; s7.z += t7.z; s7.w += t7.w;
    }
    float4 r;
    r.x = ((s0.x + s1.x) + (s2.x + s3.x)) + ((s4.x + s5.x) + (s6.x + s7.x));
    r.y = ((s0.y + s1.y) + (s2.y + s3.y)) + ((s4.y + s5.y) + (s6.y + s7.y));
    r.z = ((s0.z + s1.z) + (s2.z + s3.z)) + ((s4.z + s5.z) + (s6.z + s7.z));
    r.w = ((s0.w + s1.w) + (s2.w + s3.w)) + ((s4.w + s5.w) + (s6.w + s7.w));
    ((float4*)g_kv)[q] = r;
}

// ---------------------------------------------------------------------------
// Kernel C: softmax over the C axis (column-strided), alpha folded in.
// ---------------------------------------------------------------------------
__global__ void softmax_kernel(const float* __restrict__ alpha)
{
    int tid = threadIdx.x;
    int b = tid >> 6;
    int d = tid & 63;
    const float* in  = &g_kv[b * (C * C) + d];
    float*       out = &g_sm[b * (C * C) + d];

    float v[C];
    float m = -3.402823466e38f;
    #pragma unroll
    for (int c = 0; c < C; ++c) { v[c] = in[c * C]; m = fmaxf(m, v[c]); }
    float sum = 0.f;
    #pragma unroll
    for (int c = 0; c < C; ++c) { v[c] = expf(v[c] - m); sum += v[c]; }
    float sc = alpha[0] / sum;
    #pragma unroll
    for (int c = 0; c < C; ++c) out[c * C] = v[c] * sc;
}

// ---------------------------------------------------------------------------
// Kernel D: out[b,r,d] = sum_c key_cur[b,r,c] * sm[b,c,d] + val_cur.
// __launch_bounds__(128,2): 255-reg cap removes the spills of the
// 128-reg-capped (128,4) variant. Same proven structure as round 5.
// 128 threads, 128 rows per block; thread = 8 rows (strided by 16) x 8 d.
// ---------------------------------------------------------------------------
__global__ __launch_bounds__(128, 2) void out_kernel(
    const float* __restrict__ key_cur, const float* __restrict__ val_cur,
    float* __restrict__ out)
{
    extern __shared__ __align__(16) float s[];
    float* s_sm  = s;                 // [c][d] 64x64, 16 KB
    float* s_key = s + C * C;         // [128][RP]

    const int b   = blockIdx.y;
    const int rb  = blockIdx.x;       // 0..127 (128 rows each)
    const int tid = threadIdx.x;
    const size_t row_base = (size_t)b * NROWS + (size_t)rb * 128;

    // sm matrix (alpha folded): 1024 float4 / 128 thr = 8 each
    const float* smg = &g_sm[b * (C * C)];
    #pragma unroll
    for (int j = 0; j < 8; ++j) {
        int q = j * 128 + tid;
        *(float4*)&s_sm[q * 4] = *(const float4*)&smg[q * 4];
    }
    // keys: 128 rows x 16 chunks = 2048 float4 / 128 thr = 16 each
    #pragma unroll
    for (int j = 0; j < 16; ++j) {
        int ch  = j * 128 + tid;
        int row = ch >> 4, c4 = ch & 15;
        *(float4*)&s_key[row * RP + c4 * 4] =
            *(const float4*)&key_cur[(row_base + row) * C + c4 * 4];
    }
    __syncthreads();

    const int rg = tid >> 3;          // 0..15: rows rg, rg+16, ..., rg+112
    const int d0 = (tid & 7) * 8;

    u64 acc[8][4];
    #pragma unroll
    for (int i = 0; i < 8; ++i)
        #pragma unroll
        for (int p = 0; p < 4; ++p) acc[i][p] = 0ull;

    #pragma unroll 2
    for (int cq = 0; cq < 16; ++cq) {
        float4 kq[8];
        #pragma unroll
        for (int i = 0; i < 8; ++i)
            kq[i] = *(const float4*)&s_key[(rg + 16 * i) * RP + cq * 4];
        #pragma unroll
        for (int cc = 0; cc < 4; ++cc) {
            ulonglong2 sa = *(const ulonglong2*)&s_sm[(cq * 4 + cc) * C + d0];
            ulonglong2 sb = *(const ulonglong2*)&s_sm[(cq * 4 + cc) * C + d0 + 4];
            #pragma unroll
            for (int i = 0; i < 8; ++i) {
                float kc = (cc == 0) ? kq[i].x : (cc == 1) ? kq[i].y
                         : (cc == 2) ? kq[i].z : kq[i].w;
                u64 kd = pack2(kc, kc);
                acc[i][0] = fma2(kd, sa.x, acc[i][0]);
                acc[i][1] = fma2(kd, sa.y, acc[i][1]);
                acc[i][2] = fma2(kd, sb.x, acc[i][2]);
                acc[i][3] = fma2(kd, sb.y, acc[i][3]);
            }
        }
    }

    #pragma unroll
    for (int i = 0; i < 8; ++i) {
        size_t base = (row_base + rg + 16 * i) * C + d0;
        float4 v0 = *(const float4*)&val_cur[base];
        float4 v1 = *(const float4*)&val_cur[base + 4];
        float2 p0 = unpack2(acc[i][0]), p1 = unpack2(acc[i][1]);
        float2 p2 = unpack2(acc[i][2]), p3 = unpack2(acc[i][3]);
        *(float4*)&out[base]     = make_float4(p0.x + v0.x, p0.y + v0.y,
                                               p1.x + v0.z, p1.y + v0.w);
        *(float4*)&out[base + 4] = make_float4(p2.x + v1.x, p2.y + v1.y,
                                               p3.x + v1.z, p3.y + v1.w);
    }
}

// ---------------------------------------------------------------------------
extern "C" void kernel_launch(void* const* d_in, const int* in_sizes, int n_in,
                              void* d_out, int out_size)
{
    const float* key_mem = (const float*)d_in[0];
    const float* val_mem = (const float*)d_in[1];
    const float* key_cur = (const float*)d_in[2];
    const float* val_cur = (const float*)d_in[3];
    const float* alpha   = (const float*)d_in[4];
    float* out = (float*)d_out;

    cudaFuncSetAttribute(kv_partial_kernel,
                         cudaFuncAttributeMaxDynamicSharedMemorySize, KV_SMEM_BYTES);
    cudaFuncSetAttribute(out_kernel,
                         cudaFuncAttributeMaxDynamicSharedMemorySize, OUT_SMEM_BYTES);

    kv_partial_kernel<<<dim3(SPLITS, NB), 256, KV_SMEM_BYTES>>>(key_mem, val_mem);
    kv_reduce_kernel<<<32, 128>>>();
    softmax_kernel<<<1, 256>>>(alpha);
    out_kernel<<<dim3(NROWS / 128, NB), 128, OUT_SMEM_BYTES>>>(key_cur, val_cur, out);
}